// round 1
// baseline (speedup 1.0000x reference)
#include <cuda_runtime.h>
#include <cstdint>

#define N_CELLS 8388608
#define N_HALO  1048576
#define N_Q_IN  12
#define N_Q_OUT 11

__global__ __launch_bounds__(256) void halo_gather_kernel(
    const float* __restrict__ fields,
    const int2*  __restrict__ src_idx,
    const float2* __restrict__ weights,
    float* __restrict__ out)
{
    int e = blockIdx.x * blockDim.x + threadIdx.x;
    if (e >= N_HALO) return;

    const int2   idx = src_idx[e];
    const float2 w   = weights[e];

    const size_t i0 = (size_t)idx.x;
    const size_t i1 = (size_t)idx.y;

    // Gather all 12 raw fields at index i0 (always needed).
    float a[N_Q_IN];
    #pragma unroll
    for (int f = 0; f < N_Q_IN; f++) {
        a[f] = __ldg(fields + (size_t)f * N_CELLS + i0);
    }

    // Second gather only when its weight is nonzero (weights are (0.5,0.5) or
    // (1.0,0.0)); predicated loads -> ~25% fewer random-gather wavefronts.
    const bool need2 = (w.y != 0.0f);
    float b[N_Q_IN];
    #pragma unroll
    for (int f = 0; f < N_Q_IN; f++) {
        b[f] = need2 ? __ldg(fields + (size_t)f * N_CELLS + i1) : 0.0f;
    }

    // Derived rows:
    //  0:u 1:v 2:b_u 3:b_v 4:h 5:hh 6:dif_h 7:h+Hb 8:eta1 9:min(k_u,k3) 10:min(k_v,k3)
    float d0[N_Q_OUT], d1[N_Q_OUT];
    d0[0] = a[0];  d1[0] = b[0];
    d0[1] = a[1];  d1[1] = b[1];
    d0[2] = a[2];  d1[2] = b[2];
    d0[3] = a[3];  d1[3] = b[3];
    d0[4] = a[4];  d1[4] = b[4];
    d0[5] = a[6];  d1[5] = b[6];
    d0[6] = a[7];  d1[6] = b[7];
    d0[7] = a[4] + a[5];          d1[7] = b[4] + b[5];
    d0[8] = a[8];  d1[8] = b[8];
    d0[9]  = fminf(a[9],  a[11]); d1[9]  = fminf(b[9],  b[11]);
    d0[10] = fminf(a[10], a[11]); d1[10] = fminf(b[10], b[11]);

    #pragma unroll
    for (int q = 0; q < N_Q_OUT; q++) {
        out[(size_t)q * N_HALO + e] = w.x * d0[q] + w.y * d1[q];
    }
}

extern "C" void kernel_launch(void* const* d_in, const int* in_sizes, int n_in,
                              void* d_out, int out_size)
{
    const float*  fields  = (const float*)d_in[0];
    const int2*   src_idx = (const int2*)d_in[1];
    const float2* weights = (const float2*)d_in[2];
    float*        out     = (float*)d_out;

    const int threads = 256;
    const int blocks  = (N_HALO + threads - 1) / threads;
    halo_gather_kernel<<<blocks, threads>>>(fields, src_idx, weights, out);
}

// round 2
// speedup vs baseline: 2.2360x; 2.2360x over previous
#include <cuda_runtime.h>
#include <cstdint>

#define N_CELLS 8388608
#define N_HALO  1048576
#define NTHREADS 256
#define NBLOCKS (N_HALO / NTHREADS)   // 4096, exact

// Scratch: gathered k3 values at (i0, i1) per halo element. 8 MB, static.
__device__ float2 g_k3[N_HALO];

// ---------------------------------------------------------------------------
// Pass A: gather k3 -> scratch, and eta1 -> out row 8
__global__ __launch_bounds__(NTHREADS) void pass_k3_eta(
    const float* __restrict__ k3f, const float* __restrict__ eta,
    const int2* __restrict__ src_idx, const float2* __restrict__ weights,
    float* __restrict__ out8)
{
    int e = blockIdx.x * NTHREADS + threadIdx.x;
    const int2   i = src_idx[e];
    const float2 w = weights[e];
    const bool n2 = (w.y != 0.0f);

    float k30 = __ldg(k3f + i.x);
    float e0  = __ldg(eta + i.x);
    float k31 = n2 ? __ldg(k3f + i.y) : 0.0f;
    float e1  = n2 ? __ldg(eta + i.y) : 0.0f;

    g_k3[e] = make_float2(k30, k31);
    out8[e] = w.x * e0 + w.y * e1;
}

// ---------------------------------------------------------------------------
// Pass B: k_u, k_v with min(., k3) from scratch -> rows 9, 10
__global__ __launch_bounds__(NTHREADS) void pass_min(
    const float* __restrict__ ku, const float* __restrict__ kv,
    const int2* __restrict__ src_idx, const float2* __restrict__ weights,
    float* __restrict__ out9, float* __restrict__ out10)
{
    int e = blockIdx.x * NTHREADS + threadIdx.x;
    const int2   i = src_idx[e];
    const float2 w = weights[e];
    const bool n2 = (w.y != 0.0f);

    float u0 = __ldg(ku + i.x);
    float v0 = __ldg(kv + i.x);
    float u1 = n2 ? __ldg(ku + i.y) : 0.0f;
    float v1 = n2 ? __ldg(kv + i.y) : 0.0f;

    const float2 k3v = g_k3[e];
    out9[e]  = w.x * fminf(u0, k3v.x) + w.y * fminf(u1, k3v.y);
    out10[e] = w.x * fminf(v0, k3v.x) + w.y * fminf(v1, k3v.y);
}

// ---------------------------------------------------------------------------
// Pass C: h, Hb -> row 4 (h) and row 7 (h+Hb; summed pre-weighting, exact)
__global__ __launch_bounds__(NTHREADS) void pass_h(
    const float* __restrict__ hf, const float* __restrict__ Hbf,
    const int2* __restrict__ src_idx, const float2* __restrict__ weights,
    float* __restrict__ out4, float* __restrict__ out7)
{
    int e = blockIdx.x * NTHREADS + threadIdx.x;
    const int2   i = src_idx[e];
    const float2 w = weights[e];
    const bool n2 = (w.y != 0.0f);

    float h0 = __ldg(hf + i.x);
    float H0 = __ldg(Hbf + i.x);
    float h1 = n2 ? __ldg(hf + i.y) : 0.0f;
    float H1 = n2 ? __ldg(Hbf + i.y) : 0.0f;

    out4[e] = w.x * h0 + w.y * h1;
    out7[e] = w.x * (h0 + H0) + w.y * (h1 + H1);
}

// ---------------------------------------------------------------------------
// Pass D: two plain fields -> two output rows
__global__ __launch_bounds__(NTHREADS) void pass_two(
    const float* __restrict__ fa, const float* __restrict__ fb,
    const int2* __restrict__ src_idx, const float2* __restrict__ weights,
    float* __restrict__ outa, float* __restrict__ outb)
{
    int e = blockIdx.x * NTHREADS + threadIdx.x;
    const int2   i = src_idx[e];
    const float2 w = weights[e];
    const bool n2 = (w.y != 0.0f);

    float a0 = __ldg(fa + i.x);
    float b0 = __ldg(fb + i.x);
    float a1 = n2 ? __ldg(fa + i.y) : 0.0f;
    float b1 = n2 ? __ldg(fb + i.y) : 0.0f;

    outa[e] = w.x * a0 + w.y * a1;
    outb[e] = w.x * b0 + w.y * b1;
}

extern "C" void kernel_launch(void* const* d_in, const int* in_sizes, int n_in,
                              void* d_out, int out_size)
{
    const float*  fields  = (const float*)d_in[0];
    const int2*   src_idx = (const int2*)d_in[1];
    const float2* weights = (const float2*)d_in[2];
    float*        out     = (float*)d_out;

    // Input field rows: 0:u 1:v 2:b_u 3:b_v 4:h 5:Hb 6:hh 7:dif_h 8:eta1 9:k_u 10:k_v 11:k3
    const float* F[12];
    for (int f = 0; f < 12; f++) F[f] = fields + (size_t)f * N_CELLS;
    float* O[11];
    for (int q = 0; q < 11; q++) O[q] = out + (size_t)q * N_HALO;

    // Sequential passes; each pass's field working set (64 MB) + idx/weights
    // (16 MB) fits in the 126 MB L2, so DRAM sees only compulsory traffic.
    pass_k3_eta<<<NBLOCKS, NTHREADS>>>(F[11], F[8], src_idx, weights, O[8]);
    pass_min   <<<NBLOCKS, NTHREADS>>>(F[9], F[10], src_idx, weights, O[9], O[10]);
    pass_h     <<<NBLOCKS, NTHREADS>>>(F[4], F[5],  src_idx, weights, O[4], O[7]);
    pass_two   <<<NBLOCKS, NTHREADS>>>(F[0], F[1],  src_idx, weights, O[0], O[1]);
    pass_two   <<<NBLOCKS, NTHREADS>>>(F[2], F[3],  src_idx, weights, O[2], O[3]);
    pass_two   <<<NBLOCKS, NTHREADS>>>(F[6], F[7],  src_idx, weights, O[5], O[6]);
}